// round 17
// baseline (speedup 1.0000x reference)
#include <cuda_runtime.h>
#include <cuda_fp16.h>
#include <math.h>

#define TOKENS 4096
#define DIM    1024
#define SEQ    2048
#define NH     16
#define NKV    4
#define HD     64
#define HIDDEN 3072
#define NE     4
#define RMS_EPS 1.1920928955078125e-07f

// ---------------- scratch ----------------------------------------------------
__device__ __half g_xn16 [TOKENS * DIM];
__device__ __half g_att16[TOKENS * DIM];
__device__ __half g_h16  [NE * TOKENS * HIDDEN];
__device__ __half g_q16 [TOKENS * DIM];
__device__ __half g_k16 [TOKENS * NKV * HD];
__device__ __half g_v16 [TOKENS * NKV * HD];
__device__ int    g_cnt[NE];
__device__ int    g_idx[NE * TOKENS];
__device__ float  g_wgt[NE * TOKENS];
__device__ __half g_wq16[DIM * DIM];
__device__ __half g_wk16[DIM * NKV * HD];
__device__ __half g_wv16[DIM * NKV * HD];
__device__ __half g_wo16[DIM * DIM];
__device__ __half g_w1h [NE * DIM * HIDDEN];
__device__ __half g_w2h [NE * HIDDEN * DIM];
__device__ __half g_w3h [NE * DIM * HIDDEN];

__device__ __forceinline__ unsigned h2u(__half2 h) {
    unsigned u;
    memcpy(&u, &h, 4);
    return u;
}
__device__ __forceinline__ unsigned smem_u32(const void* p) {
    return (unsigned)__cvta_generic_to_shared(p);
}
__device__ __forceinline__ void cp16(unsigned dst, const void* src, int sz) {
    asm volatile("cp.async.cg.shared.global [%0], [%1], 16, %2;"
                 :: "r"(dst), "l"(src), "r"(sz));
}
__device__ __forceinline__ void cp_commit() {
    asm volatile("cp.async.commit_group;");
}
template<int N> __device__ __forceinline__ void cp_wait() {
    asm volatile("cp.async.wait_group %0;" :: "n"(N));
}
__device__ __forceinline__ void ldsm_x4(unsigned& r0, unsigned& r1,
                                        unsigned& r2, unsigned& r3, unsigned a) {
    asm volatile("ldmatrix.sync.aligned.m8n8.x4.shared.b16 {%0,%1,%2,%3}, [%4];"
                 : "=r"(r0), "=r"(r1), "=r"(r2), "=r"(r3) : "r"(a));
}
__device__ __forceinline__ void ldsm_x4t(unsigned& r0, unsigned& r1,
                                         unsigned& r2, unsigned& r3, unsigned a) {
    asm volatile("ldmatrix.sync.aligned.m8n8.x4.trans.shared.b16 {%0,%1,%2,%3}, [%4];"
                 : "=r"(r0), "=r"(r1), "=r"(r2), "=r"(r3) : "r"(a));
}
__device__ __forceinline__ void mma_f16(float c[4], unsigned a0, unsigned a1,
                                        unsigned a2, unsigned a3,
                                        unsigned b0, unsigned b1) {
    asm volatile("mma.sync.aligned.m16n8k16.row.col.f32.f16.f16.f32 "
        "{%0,%1,%2,%3}, {%4,%5,%6,%7}, {%8,%9}, {%0,%1,%2,%3};"
        : "+f"(c[0]), "+f"(c[1]), "+f"(c[2]), "+f"(c[3])
        : "r"(a0), "r"(a1), "r"(a2), "r"(a3), "r"(b0), "r"(b1));
}

// ------- fused (weight conversion + rmsnorm1) in ONE launch -------------------
#define CONVB 39424   /* 10092544 float4 / 256 */
__global__ void conv_rms_kernel(const float* __restrict__ wq, const float* __restrict__ wk,
                                const float* __restrict__ wv, const float* __restrict__ wo,
                                const float* __restrict__ w1, const float* __restrict__ w2,
                                const float* __restrict__ w3,
                                const float* __restrict__ x, const float* __restrict__ g1) {
    if (blockIdx.x < CONVB) {
        long i = (long)blockIdx.x * blockDim.x + threadIdx.x;
        const float* s; __half* d; long off;
        if      (i < 262144L)  { s = wq; d = g_wq16; off = i; }
        else if (i < 327680L)  { s = wk; d = g_wk16; off = i - 262144L; }
        else if (i < 393216L)  { s = wv; d = g_wv16; off = i - 327680L; }
        else if (i < 655360L)  { s = wo; d = g_wo16; off = i - 393216L; }
        else if (i < 3801088L) { s = w1; d = g_w1h;  off = i - 655360L; }
        else if (i < 6946816L) { s = w2; d = g_w2h;  off = i - 3801088L; }
        else                   { s = w3; d = g_w3h;  off = i - 6946816L; }
        float4 v = ((const float4*)s)[off];
        __half2* dp = (__half2*)(d + off * 4);
        dp[0] = __floats2half2_rn(v.x, v.y);
        dp[1] = __floats2half2_rn(v.z, v.w);
        return;
    }
    int t = blockIdx.x - CONVB, tid = threadIdx.x;
    if (t == 0 && tid < NE) g_cnt[tid] = 0;
    const float* xr = x + (size_t)t * DIM;
    float ss = 0.f;
    for (int i = tid; i < DIM; i += 256) { float v = xr[i]; ss += v * v; }
    #pragma unroll
    for (int o2 = 16; o2; o2 >>= 1) ss += __shfl_xor_sync(0xffffffffu, ss, o2);
    __shared__ float sw[8];
    if ((tid & 31) == 0) sw[tid >> 5] = ss;
    __syncthreads();
    if (tid < 8) {
        float v = sw[tid];
        #pragma unroll
        for (int o2 = 4; o2; o2 >>= 1) v += __shfl_xor_sync(0xffu, v, o2);
        if (tid == 0) sw[0] = v;
    }
    __syncthreads();
    float r = rsqrtf(sw[0] * (1.0f / DIM) + RMS_EPS);
    __half* orow = g_xn16 + (size_t)t * DIM;
    for (int i = tid; i < DIM; i += 256)
        orow[i] = __float2half_rn(xr[i] * r * g1[i]);
}

// ---------------- RMSNorm2 -> fp16 + fused MoE gate ---------------------------
__global__ void rmsnorm_kernel(const float* __restrict__ x, const float* __restrict__ g,
                               __half* __restrict__ o, const float* __restrict__ gate) {
    int t = blockIdx.x, tid = threadIdx.x;
    const float* xr = x + (size_t)t * DIM;
    float ss = 0.f;
    for (int i = tid; i < DIM; i += 256) { float v = xr[i]; ss += v * v; }
    #pragma unroll
    for (int o2 = 16; o2; o2 >>= 1) ss += __shfl_xor_sync(0xffffffffu, ss, o2);
    __shared__ float sw[8];
    __shared__ float sg[8][NE];
    if ((tid & 31) == 0) sw[tid >> 5] = ss;
    __syncthreads();
    if (tid < 8) {
        float v = sw[tid];
        #pragma unroll
        for (int o2 = 4; o2; o2 >>= 1) v += __shfl_xor_sync(0xffu, v, o2);
        if (tid == 0) sw[0] = v;
    }
    __syncthreads();
    float r = rsqrtf(sw[0] * (1.0f / DIM) + RMS_EPS);
    __half* orow = o + (size_t)t * DIM;
    float a0 = 0.f, a1 = 0.f, a2 = 0.f, a3 = 0.f;
    for (int i = tid; i < DIM; i += 256) {
        float val = xr[i] * r * g[i];
        orow[i] = __float2half_rn(val);
        const float* gr = gate + (size_t)i * NE;
        a0 += val * gr[0]; a1 += val * gr[1]; a2 += val * gr[2]; a3 += val * gr[3];
    }
    #pragma unroll
    for (int o2 = 16; o2; o2 >>= 1) {
        a0 += __shfl_xor_sync(0xffffffffu, a0, o2);
        a1 += __shfl_xor_sync(0xffffffffu, a1, o2);
        a2 += __shfl_xor_sync(0xffffffffu, a2, o2);
        a3 += __shfl_xor_sync(0xffffffffu, a3, o2);
    }
    if ((tid & 31) == 0) {
        int w = tid >> 5;
        sg[w][0] = a0; sg[w][1] = a1; sg[w][2] = a2; sg[w][3] = a3;
    }
    __syncthreads();
    if (tid == 0) {
        float p[NE];
        #pragma unroll
        for (int e = 0; e < NE; e++) {
            float s = 0.f;
            #pragma unroll
            for (int w = 0; w < 8; w++) s += sg[w][e];
            p[e] = s;
        }
        float mx = fmaxf(fmaxf(p[0], p[1]), fmaxf(p[2], p[3]));
        #pragma unroll
        for (int e = 0; e < NE; e++) p[e] = __expf(p[e] - mx);
        int e0 = 0;
        #pragma unroll
        for (int e = 1; e < NE; e++) if (p[e] > p[e0]) e0 = e;
        int e1 = -1;
        #pragma unroll
        for (int e = 0; e < NE; e++) if (e != e0 && (e1 < 0 || p[e] > p[e1])) e1 = e;
        float w0 = p[e0], w1 = p[e1], ws = p[e0] + p[e1];
        w0 /= ws; w1 /= ws;
        int s0 = atomicAdd(&g_cnt[e0], 1);
        g_idx[e0 * TOKENS + s0] = t; g_wgt[e0 * TOKENS + s0] = w0;
        int s1 = atomicAdd(&g_cnt[e1], 1);
        g_idx[e1 * TOKENS + s1] = t; g_wgt[e1 * TOKENS + s1] = w1;
    }
}

// ---------------- fp16 GEMM: 128x128x32, 4-stage, 1 sync/iter ----------------
#define TM 128
#define TN 128
#define SAB 80
#define SBB 272
#define A_STG (128 * SAB)
#define B_STG (32 * SBB)
#define STG   (A_STG + B_STG)
#define GEMM_SMEM_B (4 * STG)

// epi: 0=Cf=acc ; 1=Cf=acc+R ; 3=atomicAdd(Cf[idx],acc*w) ; 4=Ch=h(acc)
__global__ void __launch_bounds__(256, 2)
gemm16_kernel(const __half* __restrict__ A, const __half* __restrict__ B,
              float* __restrict__ Cf, __half* __restrict__ Ch,
              const float* __restrict__ R,
              int M, int N, int K,
              const int* __restrict__ cnt,
              const int* __restrict__ gidx, const float* __restrict__ gwgt,
              int epi, int gatherA,
              const __half* __restrict__ B2, const __half* __restrict__ B3,
              __half* __restrict__ Ch2, __half* __restrict__ Ch3, int qkv,
              long aStride, long bStride, long cStride, int kSplit) {
    int ez = blockIdx.z;
    int kh = 0;
    if (kSplit) { kh = ez & 1; ez >>= 1; }
    if (cnt)  cnt  += ez;
    if (gidx) gidx += (size_t)ez * TOKENS;
    if (gwgt) gwgt += (size_t)ez * TOKENS;
    A += (size_t)ez * aStride;
    B += (size_t)ez * bStride;
    if (Cf) Cf += (size_t)ez * cStride;
    if (Ch) Ch += (size_t)ez * cStride;

    int Meff = cnt ? *cnt : M;
    int rowBase = blockIdx.y * TM;
    if (rowBase >= Meff) return;

    extern __shared__ __align__(16) char gsm[];
    unsigned sm0 = smem_u32(gsm);

    int tid  = threadIdx.x;
    int lane = tid & 31;
    int wid  = tid >> 5;
    int wm   = wid & 1;
    int wn   = wid >> 1;
    int nBase = blockIdx.x * TN;

    const __half* Bq = B; float* Cq = Cf; __half* ChR = Ch; int ld = N; int nLoc = nBase;
    if (qkv) {
        if (nBase >= 1280)      { Bq = B3; ChR = Ch3; ld = 256;  nLoc = nBase - 1280; }
        else if (nBase >= 1024) { Bq = B2; ChR = Ch2; ld = 256;  nLoc = nBase - 1024; }
        else                    {                     ld = 1024; }
    }

    int Kloop = kSplit ? (K >> 1) : K;
    int kOff  = kh * Kloop;

    float acc[4][4][4];
    #pragma unroll
    for (int i = 0; i < 4; i++)
        #pragma unroll
        for (int j = 0; j < 4; j++)
            #pragma unroll
            for (int q = 0; q < 4; q++) acc[i][j][q] = 0.f;

    const __half* aP[2]; unsigned aO[2]; int aSz[2];
    const __half* bP[2]; unsigned bO[2];
    #pragma unroll
    for (int s = 0; s < 2; s++) {
        int f = tid + s * 256;
        int ar = f >> 2, ac = f & 3;
        int row = rowBase + ar;
        bool ok = row < Meff;
        long src = 0;
        if (ok) src = gatherA ? (long)gidx[row] : (long)row;
        aP[s] = A + src * (size_t)K + kOff + ac * 8;
        aSz[s] = ok ? 16 : 0;
        aO[s] = (unsigned)(ar * SAB + ac * 16);
        int br = f >> 4, bc = f & 15;
        bP[s] = Bq + (size_t)(br + kOff) * ld + nLoc + bc * 8;
        bO[s] = (unsigned)(A_STG + br * SBB + bc * 16);
    }

    int nIter = Kloop / 32;
    #pragma unroll
    for (int p = 0; p < 3; p++) {
        if (p < nIter) {
            unsigned sb = sm0 + p * STG;
            int kt = p * 32;
            #pragma unroll
            for (int s = 0; s < 2; s++) {
                cp16(sb + aO[s], aP[s] + kt, aSz[s]);
                cp16(sb + bO[s], bP[s] + (size_t)kt * ld, 16);
            }
        }
        cp_commit();
    }

    int rA = (lane & 7) + ((lane >> 3) & 1) * 8;
    int gA = lane >> 4;
    unsigned aLane = (unsigned)((wm * 64 + rA) * SAB + gA * 16);
    unsigned bLane = (unsigned)(A_STG + ((lane & 7) + ((lane >> 3) & 1) * 8) * SBB
                                + (wn * 32 + (lane >> 4) * 8) * 2);

    int st = 0;
    for (int it = 0; it < nIter; it++) {
        cp_wait<2>();
        __syncthreads();
        unsigned sb = sm0 + st * STG;

        #pragma unroll
        for (int k16 = 0; k16 < 2; k16++) {
            unsigned bf[4][2];
            #pragma unroll
            for (int jp = 0; jp < 2; jp++) {
                unsigned b0, b1, b2, b3;
                ldsm_x4t(b0, b1, b2, b3,
                         sb + bLane + (unsigned)(k16 * 16 * SBB + jp * 32));
                bf[jp * 2][0] = b0; bf[jp * 2][1] = b1;
                bf[jp * 2 + 1][0] = b2; bf[jp * 2 + 1][1] = b3;
            }
            #pragma unroll
            for (int i = 0; i < 4; i++) {
                unsigned a0, a1, a2, a3;
                ldsm_x4(a0, a1, a2, a3,
                        sb + aLane + (unsigned)(i * 16 * SAB + k16 * 32));
                #pragma unroll
                for (int j = 0; j < 4; j++)
                    mma_f16(acc[i][j], a0, a1, a2, a3, bf[j][0], bf[j][1]);
            }
        }

        if (it + 3 < nIter) {
            unsigned sn = sm0 + ((st + 3) & 3) * STG;
            int kt = (it + 3) * 32;
            #pragma unroll
            for (int s = 0; s < 2; s++) {
                cp16(sn + aO[s], aP[s] + kt, aSz[s]);
                cp16(sn + bO[s], bP[s] + (size_t)kt * ld, 16);
            }
        }
        cp_commit();
        st = (st + 1) & 3;
    }

    int r = lane >> 2, c = lane & 3;
    #pragma unroll
    for (int i = 0; i < 4; i++) {
        int rbase = rowBase + wm * 64 + i * 16 + r;
        #pragma unroll
        for (int half = 0; half < 2; half++) {
            int rr = rbase + half * 8;
            if (rr >= Meff) continue;
            int tok = 0; float w = 0.f;
            if (epi == 3) { tok = gidx[rr]; w = gwgt[rr]; }
            #pragma unroll
            for (int j = 0; j < 4; j++) {
                int col = nLoc + wn * 32 + j * 8 + (c << 1);
                float v0 = acc[i][j][half * 2];
                float v1 = acc[i][j][half * 2 + 1];
                if (epi == 0) {
                    *(float2*)(Cq + (size_t)rr * ld + col) = make_float2(v0, v1);
                } else if (epi == 1) {
                    float2 rv = *(const float2*)(R + (size_t)rr * ld + col);
                    *(float2*)(Cq + (size_t)rr * ld + col) =
                        make_float2(v0 + rv.x, v1 + rv.y);
                } else if (epi == 3) {
                    float* cp = Cq + (size_t)tok * ld + col;
                    atomicAdd(cp,     v0 * w);
                    atomicAdd(cp + 1, v1 * w);
                } else {
                    *(__half2*)(ChR + (size_t)rr * ld + col) = __floats2half2_rn(v0, v1);
                }
            }
        }
    }
}

// ---------------- dual GEMM: h = silu(x@w1) * (x@w3), 128x64 tile, 4-stage ---
#define D_A_STG 10240
#define D_B_STG 4608
#define D_STG (D_A_STG + 2 * D_B_STG)
#define DUAL_SMEM_B (4 * D_STG)

__global__ void __launch_bounds__(256, 2)
gemm16_dual_kernel(const __half* __restrict__ A, const __half* __restrict__ B1,
                   const __half* __restrict__ B3, __half* __restrict__ H,
                   const int* __restrict__ cnt, const int* __restrict__ gidx,
                   long bStride, long hStride) {
    int ez = blockIdx.z;
    cnt  += ez;
    gidx += (size_t)ez * TOKENS;
    B1 += (size_t)ez * bStride;
    B3 += (size_t)ez * bStride;
    H  += (size_t)ez * hStride;
    int Meff = *cnt;
    int rowBase = blockIdx.y * 128;
    if (rowBase >= Meff) return;

    extern __shared__ __align__(16) char gsm[];
    unsigned sm0 = smem_u32(gsm);

    int tid  = threadIdx.x;
    int lane = tid & 31;
    int wid  = tid >> 5;
    int wm   = wid & 1;
    int wn   = wid >> 1;
    int nBase = blockIdx.x * 64;

    float a1[4][2][4], a3[4][2][4];
    #pragma unroll
    for (int i = 0; i < 4; i++)
        #pragma unroll
        for (int j = 0; j < 2; j++)
            #pragma unroll
            for (int q = 0; q < 4; q++) { a1[i][j][q] = 0.f; a3[i][j][q] = 0.f; }

    const __half* aP[2]; unsigned aO[2]; int aSz[2];
    const __half* bP[2]; unsigned bO[2];
    #pragma unroll
    for (int s = 0; s < 2; s++) {
        int f = tid + s * 256;
        int ar = f >> 2, ac = f & 3;
        int row = rowBase + ar;
        bool ok = row < Meff;
        long src = 0;
        if (ok) src = (long)gidx[row];
        aP[s] = A + src * (size_t)DIM + ac * 8;
        aSz[s] = ok ? 16 : 0;
        aO[s] = (unsigned)(ar * 80 + ac * 16);
        int mat = f >> 8, fr = f & 255;
        int br = fr >> 3, bc = fr & 7;
        bP[s] = (mat ? B3 : B1) + (size_t)br * HIDDEN + nBase + bc * 8;
        bO[s] = (unsigned)(D_A_STG + mat * D_B_STG + br * 144 + bc * 16);
    }

    const int nIter = DIM / 32;
    #pragma unroll
    for (int p = 0; p < 3; p++) {
        unsigned sb = sm0 + p * D_STG;
        int kt = p * 32;
        #pragma unroll
        for (int s = 0; s < 2; s++) {
            cp16(sb + aO[s], aP[s] + kt, aSz[s]);
            cp16(sb + bO[s], bP[s] + (size_t)kt * HIDDEN, 16);
        }
        cp_commit();
    }

    int rA = (lane & 7) + ((lane >> 3) & 1) * 8;
    int gA = lane >> 4;
    unsigned aLane = (unsigned)((wm * 64 + rA) * 80 + gA * 16);
    unsigned bLane = (unsigned)(D_A_STG + rA * 144 + (wn * 16 + gA * 8) * 2);

    int st = 0;
    for (int it = 0; it < nIter; it++) {
        cp_wait<2>();
        __syncthreads();
        unsigned sb = sm0 + st * D_STG;

        #pragma unroll
        for (int k16 = 0; k16 < 2; k16++) {
            unsigned bf1[2][2], bf3[2][2];
            {
                unsigned b0, b1, b2, b3;
                ldsm_x4t(b0, b1, b2, b3, sb + bLane + (unsigned)(k16 * 16 * 144));
                bf1[0][0] = b0; bf1[0][1] = b1; bf1[1][0] = b2; bf1[1][1] = b3;
                ldsm_x4t(b0, b1, b2, b3,
                         sb + bLane + (unsigned)(D_B_STG + k16 * 16 * 144));
                bf3[0][0] = b0; bf3[0][1] = b1; bf3[1][0] = b2; bf3[1][1] = b3;
            }
            #pragma unroll
            for (int i = 0; i < 4; i++) {
                unsigned x0, x1, x2, x3;
                ldsm_x4(x0, x1, x2, x3,
                        sb + aLane + (unsigned)(i * 16 * 80 + k16 * 32));
                #pragma unroll
                for (int jp = 0; jp < 2; jp++) {
                    mma_f16(a1[i][jp], x0, x1, x2, x3, bf1[jp][0], bf1[jp][1]);
                    mma_f16(a3[i][jp], x0, x1, x2, x3, bf3[jp][0], bf3[jp][1]);
                }
            }
        }

        if (it + 3 < nIter) {
            unsigned sn = sm0 + ((st + 3) & 3) * D_STG;
            int kt = (it + 3) * 32;
            #pragma unroll
            for (int s = 0; s < 2; s++) {
                cp16(sn + aO[s], aP[s] + kt, aSz[s]);
                cp16(sn + bO[s], bP[s] + (size_t)kt * HIDDEN, 16);
            }
        }
        cp_commit();
        st = (st + 1) & 3;
    }

    int r = lane >> 2, c = lane & 3;
    #pragma unroll
    for (int i = 0; i < 4; i++) {
        int rbase = rowBase + wm * 64 + i * 16 + r;
        #pragma unroll
        for (int half = 0; half < 2; half++) {
            int rr = rbase + half * 8;
            if (rr >= Meff) continue;
            #pragma unroll
            for (int jp = 0; jp < 2; jp++) {
                int col = nBase + wn * 16 + jp * 8 + (c << 1);
                float u0 = a1[i][jp][half * 2],     u1 = a1[i][jp][half * 2 + 1];
                float v0 = a3[i][jp][half * 2],     v1 = a3[i][jp][half * 2 + 1];
                float s0 = u0 / (1.f + __expf(-u0)) * v0;
                float s1 = u1 / (1.f + __expf(-u1)) * v1;
                *(__half2*)(H + (size_t)rr * HIDDEN + col) = __floats2half2_rn(s0, s1);
            }
        }
    }
}

// ---------------- RoPE on fp16 k only (q fused into flash) -------------------
__global__ void ropek_kernel(__half* __restrict__ k) {
    int id = blockIdx.x * blockDim.x + threadIdx.x;
    if (id >= TOKENS * NKV * 32) return;
    int t = id >> 7; int r = id & 127; int h = r >> 5; int i = r & 31;
    __half* base = k + ((size_t)t * NKV + h) * HD;
    int pos = t & (SEQ - 1);
    float inv = exp2f(-(float)i * 0.4152410118609203f);
    float fr = (float)pos * inv;
    float sn, cs;
    sincosf(fr, &sn, &cs);
    float x1 = __half2float(base[i]), x2 = __half2float(base[i + 32]);
    base[i]      = __float2half_rn(x1 * cs - x2 * sn);
    base[i + 32] = __float2half_rn(x2 * cs + x1 * sn);
}

// ---------------- fp16 flash attention (q-RoPE fused at Q load) --------------
#define HST 72
#define KOFF 0
#define VOFF (2 * 64 * HST)
#define POFF (VOFF + 2 * 64 * HST)
#define KTB  (64 * HST * 2)
#define FLASH_SMEM_B ((POFF + 128 * HST) * 2)

__global__ void __launch_bounds__(256, 2)
flash16_kernel(const __half* __restrict__ q, const __half* __restrict__ k,
               const __half* __restrict__ v, __half* __restrict__ att) {
    extern __shared__ __half hs[];
    int qi = (SEQ / 128 - 1) - blockIdx.x;
    int h = blockIdx.y, b = blockIdx.z, hk = h >> 2;
    int qbase = qi * 128;
    int tid = threadIdx.x, lane = tid & 31, w = tid >> 5;
    int lr = lane >> 2, cq = lane & 3;
    int row0 = w * 16 + lr, row1 = row0 + 8;
    unsigned base = smem_u32(hs);

    int rA = (lane & 7) + ((lane >> 3) & 1) * 8;
    int cA = ((lane >> 4) & 1) * 8;
    unsigned pLane = base + (unsigned)((POFF + (w * 16 + rA) * HST + cA) * 2);
    unsigned kLane = base + (unsigned)((KOFF + rA * HST + cA) * 2);
    int gB = lane >> 4;
    unsigned vLane = base + (unsigned)((VOFF + rA * HST + gB * 8) * 2);

    const size_t kvs = (size_t)NKV * HD;
    const __half* kb = k + ((size_t)(b * SEQ) * NKV + hk) * HD;
    const __half* vb = v + ((size_t)(b * SEQ) * NKV + hk) * HD;

    unsigned kDst[2], vDst[2]; const __half* kSrc[2]; const __half* vSrc[2];
    #pragma unroll
    for (int s = 0; s < 2; s++) {
        int idx = tid + s * 256;
        int rr = idx >> 3, cc = idx & 7;
        kDst[s] = base + (unsigned)((KOFF + rr * HST + cc * 8) * 2);
        vDst[s] = base + (unsigned)((VOFF + rr * HST + cc * 8) * 2);
        kSrc[s] = kb + (size_t)rr * kvs + cc * 8;
        vSrc[s] = vb + (size_t)rr * kvs + cc * 8;
    }

    // Q fragments: load raw q16, apply RoPE in fp32, scale by 0.125
    unsigned qa[4][4];
    {
        const __half* q0 = q + ((size_t)(b * SEQ + qbase + row0) * NH + h) * HD;
        const __half* q1 = q + ((size_t)(b * SEQ + qbase + row1) * NH + h) * HD;
        const __half* qp[2] = {q0, q1};
        float qv[2][4][4];
        #pragma unroll
        for (int r2 = 0; r2 < 2; r2++)
            #pragma unroll
            for (int g = 0; g < 4; g++) {
                int kk = g * 16 + cq * 2;
                float2 aa = __half22float2(*(const __half2*)(qp[r2] + kk));
                float2 bb = __half22float2(*(const __half2*)(qp[r2] + kk + 8));
                qv[r2][g][0] = aa.x; qv[r2][g][1] = aa.y;
                qv[r2][g][2] = bb.x; qv[r2][g][3] = bb.y;
            }
        int posr[2] = {qbase + row0, qbase + row1};
        #pragma unroll
        for (int r2 = 0; r2 < 2; r2++)
            #pragma unroll
            for (int g = 0; g < 2; g++)
                #pragma unroll
                for (int s2 = 0; s2 < 4; s2++) {
                    int c = g * 16 + cq * 2 + (s2 < 2 ? s2 : s2 + 6);
                    float fr = (float)posr[r2] * exp2f(-(float)c * 0.4152410118609203f);
                    float sn, cs;
                    sincosf(fr, &sn, &cs);
                    float x1 = qv[r2][g][s2], x2 = qv[r2][g + 2][s2];
                    qv[r2][g][s2]     = (x1 * cs - x2 * sn) * 0.125f;
                    qv[r2][g + 2][s2] = (x2 * cs + x1 * sn) * 0.125f;
                }
        #pragma unroll
        for (int g = 0; g < 4; g++) {
            qa[g][0] = h2u(__floats2half2_rn(qv[0][g][0], qv[0][g][1]));
            qa[g][1] = h2u(__floats2half2_rn(qv[1][g][0], qv[1][g][1]));
            qa[g][2] = h2u(__floats2half2_rn(qv[0][g][2], qv[0][g][3]));
            qa[g][3] = h2u(__floats2half2_rn(qv[1][g][2], qv[1][g][3]));
        }
    }

    float oacc[8][4];
    #pragma unroll
    for (int nf = 0; nf < 8; nf++)
        #pragma unroll
        for (int t2 = 0; t2 < 4; t2++) oacc[nf][t2] = 0.f;
    float m0 = -3.0e38f, m1 = -3.0e38f, l0 = 0.f, l1 = 0.f;
    int nkt = 2 * qi + 2;

    #pragma unroll
    for (int s = 0; s < 2; s++) { cp16(kDst[s], kSrc[s], 16); cp16(vDst[s], vSrc[s], 16); }
    cp_commit();

    for (int kt = 0; kt < nkt; kt++) {
        int cur = kt & 1;
        __syncthreads();
        if (kt + 1 < nkt) {
            size_t off = (size_t)(kt + 1) * 64 * kvs;
            int nb = cur ^ 1;
            #pragma unroll
            for (int s = 0; s < 2; s++) {
                cp16(kDst[s] + nb * KTB, kSrc[s] + off, 16);
                cp16(vDst[s] + nb * KTB, vSrc[s] + off, 16);
            }
            cp_commit();
            cp_wait<1>();
        } else cp_wait<0>();
        __syncthreads();

        float s[8][4];
        #pragma unroll
        for (int nf = 0; nf < 8; nf++)
            #pragma unroll
            for (int t2 = 0; t2 < 4; t2++) s[nf][t2] = 0.f;
        #pragma unroll
        for (int g = 0; g < 4; g++) {
            #pragma unroll
            for (int nfp = 0; nfp < 4; nfp++) {
                unsigned b0, b1, b2, b3;
                ldsm_x4(b0, b1, b2, b3,
                        kLane + cur * KTB + (unsigned)(nfp * 16 * HST * 2 + g * 32));
                mma_f16(s[2 * nfp],     qa[g][0], qa[g][1], qa[g][2], qa[g][3], b0, b2);
                mma_f16(s[2 * nfp + 1], qa[g][0], qa[g][1], qa[g][2], qa[g][3], b1, b3);
            }
        }

        if (kt + 2 >= nkt) {
            int dk = kt * 64 - qbase;
            #pragma unroll
            for (int nf = 0; nf < 8; nf++) {
                int c0 = nf * 8 + cq * 2 + dk;
                if (c0     > row0) s[nf][0] = -3.0e38f;
                if (c0 + 1 > row0) s[nf][1] = -3.0e38f;
                if (c0     > row1) s[nf][2] = -3.0e38f;
                if (c0 + 1 > row1) s[nf][3] = -3.0e38f;
            }
        }

        float rm0 = -3.0e38f, rm1 = -3.0e38f;
        #pragma unroll
        for (int nf = 0; nf < 8; nf++) {
            rm0 = fmaxf(rm0, fmaxf(s[nf][0], s[nf][1]));
            rm1 = fmaxf(rm1, fmaxf(s[nf][2], s[nf][3]));
        }
        rm0 = fmaxf(rm0, __shfl_xor_sync(0xffffffffu, rm0, 1));
        rm0 = fmaxf(rm0, __shfl_xor_sync(0xffffffffu, rm0, 2));
        rm1 = fmaxf(rm1, __shfl_xor_sync(0xffffffffu, rm1, 1));
        rm1 = fmaxf(rm1, __shfl_xor_sync(0xffffffffu, rm1, 2));
        float mn0 = fmaxf(m0, rm0), mn1 = fmaxf(m1, rm1);
        float sc0 = __expf(m0 - mn0), sc1 = __expf(m1 - mn1);
        m0 = mn0; m1 = mn1;
        l0 *= sc0; l1 *= sc1;
        __half* Pb = hs + POFF;
        #pragma unroll
        for (int nf = 0; nf < 8; nf++) {
            float p0 = __expf(s[nf][0] - mn0), p1 = __expf(s[nf][1] - mn0);
            float p2 = __expf(s[nf][2] - mn1), p3 = __expf(s[nf][3] - mn1);
            l0 += p0 + p1; l1 += p2 + p3;
            int c0 = nf * 8 + cq * 2;
            *(__half2*)(Pb + row0 * HST + c0) = __floats2half2_rn(p0, p1);
            *(__half2*)(Pb + row1 * HST + c0) = __floats2half2_rn(p2, p3);
            oacc[nf][0] *= sc0; oacc[nf][1] *= sc0;
            oacc[nf][2] *= sc1; oacc[nf][3] *= sc1;
        }
        __syncwarp();

        #pragma unroll
        for (int g = 0; g < 4; g++) {
            unsigned a0, a1, a2, a3;
            ldsm_x4(a0, a1, a2, a3, pLane + (unsigned)(g * 32));
            #pragma unroll
            for (int jp = 0; jp < 4; jp++) {
                unsigned b0, b1, b2, b3;
                ldsm_x4t(b0, b1, b2, b3,
                         vLane + cur * KTB + (unsigned)(g * 16 * HST * 2 + jp * 32));
                mma_f16(oacc[2 * jp],     a0, a1, a2, a3, b0, b1);
                mma_f16(oacc[2 * jp + 1], a0, a1, a2, a3, b2, b3);
            }
        }
    }

    l0 += __shfl_xor_sync(0xffffffffu, l0, 1);
    l0 += __shfl_xor_sync(0xffffffffu, l0, 2);
    l1 += __shfl_xor_sync(0xffffffffu, l1, 1);
    l1 += __shfl_xor_sync(0xffffffffu, l1, 2);
    float i0 = 1.f / l0, i1 = 1.f / l1;
    __half* o0 = att + ((size_t)(b * SEQ + qbase + row0) * NH + h) * HD;
    __half* o1 = att + ((size_t)(b * SEQ + qbase + row1) * NH + h) * HD;
    #pragma unroll
    for (int nf = 0; nf < 8; nf++) {
        int c0 = nf * 8 + cq * 2;
        *(__half2*)(o0 + c0) = __floats2half2_rn(oacc[nf][0] * i0, oacc[nf][1] * i0);
        *(__half2*)(o1 + c0) = __floats2half2_rn(oacc[nf][2] * i1, oacc[nf][3] * i1);
    }
}

// ---------------- launch ------------------------------------------------------
static inline void launch_gemm(const __half* A, const __half* B, float* Cf, __half* Ch,
                               const float* R, int M, int N, int K,
                               const int* cnt, const int* gi, const float* gw,
                               int epi, int gat, int nz, long aS, long bS, long cS,
                               int kSplit) {
    dim3 grid(N / TN, (M + TM - 1) / TM, nz);
    gemm16_kernel<<<grid, 256, GEMM_SMEM_B>>>(A, B, Cf, Ch, R, M, N, K, cnt, gi, gw,
                                              epi, gat, nullptr, nullptr, nullptr,
                                              nullptr, 0, aS, bS, cS, kSplit);
}

extern "C" void kernel_launch(void* const* d_in, const int* in_sizes, int n_in,
                              void* d_out, int out_size) {
    const float* x    = (const float*)d_in[0];
    const float* g1   = (const float*)d_in[1];
    const float* g2   = (const float*)d_in[2];
    const float* wq   = (const float*)d_in[3];
    const float* wk   = (const float*)d_in[4];
    const float* wv   = (const float*)d_in[5];
    const float* wo   = (const float*)d_in[6];
    const float* gate = (const float*)d_in[7];
    const float* w1   = (const float*)d_in[8];
    const float* w2   = (const float*)d_in[9];
    const float* w3   = (const float*)d_in[10];
    float* out = (float*)d_out;

    __half *xn16, *att16, *h16, *q16, *k16, *v16;
    __half *wq16, *wk16, *wv16, *wo16, *w1h, *w2h, *w3h;
    float *wgt;
    int *cnt, *idx;
    cudaGetSymbolAddress((void**)&xn16,  g_xn16);
    cudaGetSymbolAddress((void**)&att16, g_att16);
    cudaGetSymbolAddress((void**)&h16,   g_h16);
    cudaGetSymbolAddress((void**)&q16, g_q16);
    cudaGetSymbolAddress((void**)&k16, g_k16);
    cudaGetSymbolAddress((void**)&v16, g_v16);
    cudaGetSymbolAddress((void**)&cnt, g_cnt);
    cudaGetSymbolAddress((void**)&idx, g_idx);
    cudaGetSymbolAddress((void**)&wgt, g_wgt);
    cudaGetSymbolAddress((void**)&wq16, g_wq16);
    cudaGetSymbolAddress((void**)&wk16, g_wk16);
    cudaGetSymbolAddress((void**)&wv16, g_wv16);
    cudaGetSymbolAddress((void**)&wo16, g_wo16);
    cudaGetSymbolAddress((void**)&w1h, g_w1h);
    cudaGetSymbolAddress((void**)&w2h, g_w2h);
    cudaGetSymbolAddress((void**)&w3h, g_w3h);

    cudaFuncSetAttribute(flash16_kernel,
                         cudaFuncAttributeMaxDynamicSharedMemorySize, FLASH_SMEM_B);
    cudaFuncSetAttribute(gemm16_kernel,
                         cudaFuncAttributeMaxDynamicSharedMemorySize, GEMM_SMEM_B);
    cudaFuncSetAttribute(gemm16_dual_kernel,
                         cudaFuncAttributeMaxDynamicSharedMemorySize, DUAL_SMEM_B);

    // 1: weight conversion + rmsnorm1 + cnt zero (one launch, independent work)
    conv_rms_kernel<<<CONVB + TOKENS, 256>>>(wq, wk, wv, wo, w1, w2, w3, x, g1);
    // 2: fused q/k/v (fp16 outputs)
    {
        dim3 grid(1536 / TN, TOKENS / TM, 1);
        gemm16_kernel<<<grid, 256, GEMM_SMEM_B>>>(xn16, wq16, nullptr, q16, nullptr,
                                                  TOKENS, 1536, DIM,
                                                  nullptr, nullptr, nullptr, 4, 0,
                                                  wk16, wv16, k16, v16, 1, 0, 0, 0, 0);
    }
    // 3: rope on k only (q rope fused into flash)
    ropek_kernel<<<(TOKENS * NKV * 32 + 255) / 256, 256>>>(k16);
    // 4: flash
    {
        dim3 grid(SEQ / 128, NH, 2);
        flash16_kernel<<<grid, 256, FLASH_SMEM_B>>>(q16, k16, v16, att16);
    }
    // 5: out = x + att @ wo
    launch_gemm(att16, wo16, out, nullptr, x, TOKENS, DIM, DIM,
                nullptr, nullptr, nullptr, 1, 0, 1, 0, 0, 0, 0);
    // 6: rmsnorm2 + gate
    rmsnorm_kernel<<<TOKENS, 256>>>(out, g2, xn16, gate);
    // 7: fused w1+w3 -> h16
    {
        dim3 grid(HIDDEN / 64, TOKENS / 128, NE);
        gemm16_dual_kernel<<<grid, 256, DUAL_SMEM_B>>>(xn16, w1h, w3h, h16, cnt, idx,
                                                       (long)DIM * HIDDEN,
                                                       (long)TOKENS * HIDDEN);
    }
    // 8: out[tok] += (h16 @ w2) * wgt  (split-K=2, atomic epilogue)
    launch_gemm(h16, w2h, out, nullptr, nullptr, TOKENS, DIM, HIDDEN,
                cnt, idx, wgt, 3, 0, NE * 2, (long)TOKENS * HIDDEN,
                (long)HIDDEN * DIM, 0, 1);
}